// round 8
// baseline (speedup 1.0000x reference)
#include <cuda_runtime.h>
#include <cuda_fp16.h>
#include <cstdint>

#define T_DIM 4096
#define H_DIM 2048

// __device__ scratch (no allocation allowed)
__device__ float  g_S [T_DIM * H_DIM];   // 32 MB: S = X @ B
__device__ __half g_Xh[T_DIM * H_DIM];   // 16 MB: X in fp16
__device__ __half g_Bt[H_DIM * H_DIM];   //  8 MB: B^T in fp16 ([n][k])

__device__ __forceinline__ float tanh_fast(float x) {
    float y;
    asm("tanh.approx.f32 %0, %1;" : "=f"(y) : "f"(x));
    return y;
}
__device__ __forceinline__ uint32_t smem_u32(const void* p) {
    return (uint32_t)__cvta_generic_to_shared(p);
}
__device__ __forceinline__ void cp16(uint32_t dst, const void* src) {
    asm volatile("cp.async.cg.shared.global [%0], [%1], 16;" :: "r"(dst), "l"(src));
}
__device__ __forceinline__ void cp_commit() {
    asm volatile("cp.async.commit_group;" ::: "memory");
}
template <int N> __device__ __forceinline__ void cp_wait() {
    asm volatile("cp.async.wait_group %0;" :: "n"(N) : "memory");
}
#define LDSM_X4(r0, r1, r2, r3, addr)                                          \
    asm volatile("ldmatrix.sync.aligned.m8n8.x4.shared.b16 {%0,%1,%2,%3}, [%4];" \
                 : "=r"(r0), "=r"(r1), "=r"(r2), "=r"(r3) : "r"(addr))

// ---------------- pre-pass 1: X fp32 -> fp16 ----------------
__global__ __launch_bounds__(256) void cvt_x_kernel(const float* __restrict__ X) {
    size_t i = ((size_t)blockIdx.x * 256 + threadIdx.x) * 4;
    float4 v = *reinterpret_cast<const float4*>(&X[i]);
    __half2 lo = __floats2half2_rn(v.x, v.y);
    __half2 hi = __floats2half2_rn(v.z, v.w);
    *reinterpret_cast<uint2*>(&g_Xh[i]) =
        make_uint2(*reinterpret_cast<uint32_t*>(&lo), *reinterpret_cast<uint32_t*>(&hi));
}

// ---------------- pre-pass 2: B fp32 [k][n] -> fp16 [n][k] ----------------
__global__ __launch_bounds__(256) void cvt_bt_kernel(const float* __restrict__ Bm) {
    __shared__ float tile[32][33];
    const int k0 = blockIdx.y * 32, n0 = blockIdx.x * 32;
    const int x = threadIdx.x & 31, y4 = (threadIdx.x >> 5) << 2;
#pragma unroll
    for (int j = 0; j < 4; j++)
        tile[y4 + j][x] = Bm[(size_t)(k0 + y4 + j) * H_DIM + n0 + x];
    __syncthreads();
#pragma unroll
    for (int j = 0; j < 4; j++)
        g_Bt[(size_t)(n0 + y4 + j) * H_DIM + k0 + x] = __float2half_rn(tile[x][y4 + j]);
}

// ---------------- GEMM: S = X @ B, fp16 m16n8k16, LDSM + cp.async ----------
// Block tile 128(M) x 256(N) x 32(K); 8 warps = 2(M) x 4(N); warp tile 64x64.
// Smem halves, row stride LDH=40 (LDSM phases conflict-free: 80B-row segments
// land on distinct 16B bank groups). Double-buffered cp.async, depth-1 prefetch.
constexpr int BM = 128, BN = 256, BK = 32;
constexpr int LDH = 40;
constexpr int A_HALFS = BM * LDH;                 // 5120
constexpr int B_HALFS = BN * LDH;                 // 10240
constexpr int BUF_BYTES = (A_HALFS + B_HALFS) * 2;  // 30720
constexpr int B_BASE = A_HALFS * 2;               // byte offset of B within buf
constexpr int SMEM_BYTES = 2 * BUF_BYTES;         // 61440
constexpr int NT = H_DIM / BK;                    // 64

__global__ __launch_bounds__(256) void gemm_f16_kernel()
{
    extern __shared__ __half sh[];
    const uint32_t sbase = smem_u32(sh);

    const int tid  = threadIdx.x;
    const int warp = tid >> 5;
    const int lane = tid & 31;
    const int bm   = blockIdx.y * BM;
    const int bn   = blockIdx.x * BN;
    const int wm   = (warp & 1) * 64;
    const int wn   = (warp >> 1) * 64;

    // cp.async mappings (16B chunks of 8 halves)
    // A: 128 rows x 4 chunks = 512; 2/thread. B: 256 rows x 4 chunks = 1024; 4/thread.
    const int ar0 = tid >> 2, ac8 = (tid & 3) << 3;
    const int ar1 = (tid + 256) >> 2;
    int br[4];
#pragma unroll
    for (int j = 0; j < 4; j++) br[j] = (tid + j * 256) >> 2;
    const int bc8 = ac8;  // same (q&3)*8 pattern

    auto issue = [&](int c, int buf) {
        const int k0 = c * BK;
        const uint32_t bo = sbase + buf * BUF_BYTES;
        cp16(bo + ar0 * 80 + ac8 * 2, &g_Xh[(size_t)(bm + ar0) * H_DIM + k0 + ac8]);
        cp16(bo + ar1 * 80 + ac8 * 2, &g_Xh[(size_t)(bm + ar1) * H_DIM + k0 + ac8]);
#pragma unroll
        for (int j = 0; j < 4; j++)
            cp16(bo + B_BASE + br[j] * 80 + bc8 * 2,
                 &g_Bt[(size_t)(bn + br[j]) * H_DIM + k0 + bc8]);
        cp_commit();
    };

    // ldmatrix lane-address byte offsets (within a buffer)
    uint32_t a_off[4], b_off[4];
#pragma unroll
    for (int mi = 0; mi < 4; mi++)
        a_off[mi] = (uint32_t)((wm + mi * 16 + (lane & 15)) * 80 + ((lane >> 4) << 4));
#pragma unroll
    for (int pi = 0; pi < 4; pi++)
        b_off[pi] = (uint32_t)(B_BASE +
            (wn + pi * 16 + (lane & 7) + ((lane >> 4) << 3)) * 80 +
            (((lane >> 3) & 1) << 4));

    float acc[4][8][4];
#pragma unroll
    for (int mi = 0; mi < 4; mi++)
#pragma unroll
        for (int ni = 0; ni < 8; ni++)
#pragma unroll
            for (int r = 0; r < 4; r++) acc[mi][ni][r] = 0.0f;

    issue(0, 0);

    for (int kt = 0; kt < NT; kt++) {
        const int buf = kt & 1;
        if (kt + 1 < NT) { issue(kt + 1, buf ^ 1); cp_wait<1>(); }
        else             { cp_wait<0>(); }
        __syncthreads();

        const uint32_t bo = sbase + buf * BUF_BYTES;
#pragma unroll
        for (int kk = 0; kk < BK; kk += 16) {
            uint32_t afr[4][4], bfr[8][2];
#pragma unroll
            for (int mi = 0; mi < 4; mi++)
                LDSM_X4(afr[mi][0], afr[mi][1], afr[mi][2], afr[mi][3],
                        bo + a_off[mi] + kk * 2);
#pragma unroll
            for (int pi = 0; pi < 4; pi++)
                LDSM_X4(bfr[2 * pi][0], bfr[2 * pi][1], bfr[2 * pi + 1][0], bfr[2 * pi + 1][1],
                        bo + b_off[pi] + kk * 2);
#pragma unroll
            for (int mi = 0; mi < 4; mi++)
#pragma unroll
                for (int ni = 0; ni < 8; ni++) {
                    asm volatile(
                        "mma.sync.aligned.m16n8k16.row.col.f32.f16.f16.f32 "
                        "{%0,%1,%2,%3},{%4,%5,%6,%7},{%8,%9},{%0,%1,%2,%3};"
                        : "+f"(acc[mi][ni][0]), "+f"(acc[mi][ni][1]),
                          "+f"(acc[mi][ni][2]), "+f"(acc[mi][ni][3])
                        : "r"(afr[mi][0]), "r"(afr[mi][1]), "r"(afr[mi][2]), "r"(afr[mi][3]),
                          "r"(bfr[ni][0]), "r"(bfr[ni][1]));
                }
        }
        __syncthreads();
    }

    // Epilogue: c0,c1 -> (row, col..col+1); c2,c3 -> (row+8, ...)
#pragma unroll
    for (int mi = 0; mi < 4; mi++) {
#pragma unroll
        for (int ni = 0; ni < 8; ni++) {
            int row = bm + wm + mi * 16 + (lane >> 2);
            int col = bn + wn + ni * 8 + ((lane & 3) << 1);
            float2 lo = make_float2(acc[mi][ni][0], acc[mi][ni][1]);
            float2 hi = make_float2(acc[mi][ni][2], acc[mi][ni][3]);
            *reinterpret_cast<float2*>(&g_S[(size_t)row * H_DIM + col])       = lo;
            *reinterpret_cast<float2*>(&g_S[(size_t)(row + 8) * H_DIM + col]) = hi;
        }
    }
}

// ---------------- chunked scan: h_t = tanh(a*h + s_t) ----------------
// |a| <= sqrt(2/2048) = 0.03125 -> chunk truncation error <= 0.03125^8 ~ 1e-12.
constexpr int CHUNK  = 32;
constexpr int WARMUP = 8;

__global__ __launch_bounds__(256) void scan_kernel(
    const float* __restrict__ a_mat, float* __restrict__ out)
{
    const int c  = blockIdx.x * blockDim.x + threadIdx.x;
    const int t0 = blockIdx.y * CHUNK;
    const float av = a_mat[c];

    float h = 0.0f;
    int tw = t0 - WARMUP;
    if (tw < 0) tw = 0;
#pragma unroll 4
    for (int t = tw; t < t0; ++t)
        h = tanh_fast(fmaf(av, h, g_S[(size_t)t * H_DIM + c]));
#pragma unroll 8
    for (int t = t0; t < t0 + CHUNK; ++t) {
        h = tanh_fast(fmaf(av, h, g_S[(size_t)t * H_DIM + c]));
        out[(size_t)t * H_DIM + c] = h;
    }
}

// ---------------- launch ----------------
extern "C" void kernel_launch(void* const* d_in, const int* in_sizes, int n_in,
                              void* d_out, int out_size)
{
    const float* x     = (const float*)d_in[0];  // (4096, 2048)
    const float* a_mat = (const float*)d_in[1];  // (2048,)
    const float* b_mat = (const float*)d_in[2];  // (2048, 2048)
    float* out = (float*)d_out;                  // (4096, 2048)

    cudaFuncSetAttribute(gemm_f16_kernel,
                         cudaFuncAttributeMaxDynamicSharedMemorySize, SMEM_BYTES);

    cvt_x_kernel<<<(T_DIM * H_DIM) / (256 * 4), 256>>>(x);
    cvt_bt_kernel<<<dim3(H_DIM / 32, H_DIM / 32), 256>>>(b_mat);

    dim3 gemm_grid(H_DIM / BN, T_DIM / BM);      // (8, 32)
    gemm_f16_kernel<<<gemm_grid, 256, SMEM_BYTES>>>();

    dim3 scan_grid(H_DIM / 256, T_DIM / CHUNK);  // (8, 128)
    scan_kernel<<<scan_grid, 256>>>(a_mat, out);
}

// round 11
// speedup vs baseline: 1.0376x; 1.0376x over previous
#include <cuda_runtime.h>
#include <cuda_fp16.h>
#include <cstdint>

#define T_DIM 4096
#define H_DIM 2048

// __device__ scratch (no allocation allowed)
__device__ float  g_S [T_DIM * H_DIM];   // 32 MB: S = X @ B
__device__ __half g_Xh[T_DIM * H_DIM];   // 16 MB: X in fp16
__device__ __half g_Bt[H_DIM * H_DIM];   //  8 MB: B^T in fp16 ([n][k])

__device__ __forceinline__ float tanh_fast(float x) {
    float y;
    asm("tanh.approx.f32 %0, %1;" : "=f"(y) : "f"(x));
    return y;
}
__device__ __forceinline__ uint32_t smem_u32(const void* p) {
    return (uint32_t)__cvta_generic_to_shared(p);
}
__device__ __forceinline__ void cp16(uint32_t dst, const void* src) {
    asm volatile("cp.async.cg.shared.global [%0], [%1], 16;" :: "r"(dst), "l"(src));
}
__device__ __forceinline__ void cp_commit() {
    asm volatile("cp.async.commit_group;" ::: "memory");
}
template <int N> __device__ __forceinline__ void cp_wait() {
    asm volatile("cp.async.wait_group %0;" :: "n"(N) : "memory");
}
#define LDSM_X4(r0, r1, r2, r3, addr)                                          \
    asm volatile("ldmatrix.sync.aligned.m8n8.x4.shared.b16 {%0,%1,%2,%3}, [%4];" \
                 : "=r"(r0), "=r"(r1), "=r"(r2), "=r"(r3) : "r"(addr))

// ---------------- pre-pass 1: X fp32 -> fp16 ----------------
__global__ __launch_bounds__(256) void cvt_x_kernel(const float* __restrict__ X) {
    size_t i = ((size_t)blockIdx.x * 256 + threadIdx.x) * 4;
    float4 v = *reinterpret_cast<const float4*>(&X[i]);
    __half2 lo = __floats2half2_rn(v.x, v.y);
    __half2 hi = __floats2half2_rn(v.z, v.w);
    *reinterpret_cast<uint2*>(&g_Xh[i]) =
        make_uint2(*reinterpret_cast<uint32_t*>(&lo), *reinterpret_cast<uint32_t*>(&hi));
}

// ---------------- pre-pass 2: B fp32 [k][n] -> fp16 [n][k] ----------------
__global__ __launch_bounds__(256) void cvt_bt_kernel(const float* __restrict__ Bm) {
    __shared__ float tile[32][33];
    const int k0 = blockIdx.y * 32, n0 = blockIdx.x * 32;
    const int x = threadIdx.x & 31, y4 = (threadIdx.x >> 5) << 2;
#pragma unroll
    for (int j = 0; j < 4; j++)
        tile[y4 + j][x] = Bm[(size_t)(k0 + y4 + j) * H_DIM + n0 + x];
    __syncthreads();
#pragma unroll
    for (int j = 0; j < 4; j++)
        g_Bt[(size_t)(n0 + y4 + j) * H_DIM + k0 + x] = __float2half_rn(tile[x][y4 + j]);
}

// ---------------- GEMM: S = X @ B, fp16 m16n8k16, LDSM + cp.async ----------
// Block tile 128(M) x 128(N) x 32(K); 8 warps = 4(M) x 2(N); warp tile 32x64.
// acc = 64 regs/thread -> __launch_bounds__(256,2) -> 2 CTAs/SM: the second
// CTA's warps fill the cp_wait/__syncthreads/LDSM bubbles at k-tile bounds.
// Smem halves, row stride LDH=40 (LDSM phases conflict-free). Double-buffered
// cp.async, depth-1 prefetch. 40 KB smem/CTA (82 KB for 2 CTAs).
constexpr int BM = 128, BN = 128, BK = 32;
constexpr int LDH = 40;
constexpr int A_HALFS = BM * LDH;                   // 5120
constexpr int B_HALFS = BN * LDH;                   // 5120
constexpr int BUF_BYTES = (A_HALFS + B_HALFS) * 2;  // 20480
constexpr int B_BASE = A_HALFS * 2;                 // byte offset of B in buf
constexpr int SMEM_BYTES = 2 * BUF_BYTES;           // 40960
constexpr int NT = H_DIM / BK;                      // 64

__global__ __launch_bounds__(256, 2) void gemm_f16_kernel()
{
    extern __shared__ __half sh[];
    const uint32_t sbase = smem_u32(sh);

    const int tid  = threadIdx.x;
    const int warp = tid >> 5;
    const int lane = tid & 31;
    const int bm   = blockIdx.y * BM;
    const int bn   = blockIdx.x * BN;
    const int wm   = (warp & 3) * 32;    // 4 M-warps
    const int wn   = (warp >> 2) * 64;   // 2 N-warps

    // cp.async: A and B tiles are both 128 rows x 32 halves = 512 x 16B chunks,
    // 2 chunks/thread each: row = chunk>>2, col8 = (chunk&3)*8 halves.
    const int r0 = tid >> 2, c8 = (tid & 3) << 3;
    const int r1 = (tid + 256) >> 2;

    auto issue = [&](int c, int buf) {
        const int k0 = c * BK;
        const uint32_t bo = sbase + buf * BUF_BYTES;
        cp16(bo + r0 * 80 + c8 * 2, &g_Xh[(size_t)(bm + r0) * H_DIM + k0 + c8]);
        cp16(bo + r1 * 80 + c8 * 2, &g_Xh[(size_t)(bm + r1) * H_DIM + k0 + c8]);
        cp16(bo + B_BASE + r0 * 80 + c8 * 2, &g_Bt[(size_t)(bn + r0) * H_DIM + k0 + c8]);
        cp16(bo + B_BASE + r1 * 80 + c8 * 2, &g_Bt[(size_t)(bn + r1) * H_DIM + k0 + c8]);
        cp_commit();
    };

    // ldmatrix lane-address byte offsets (within a buffer)
    uint32_t a_off[2], b_off[4];
#pragma unroll
    for (int mi = 0; mi < 2; mi++)
        a_off[mi] = (uint32_t)((wm + mi * 16 + (lane & 15)) * 80 + ((lane >> 4) << 4));
#pragma unroll
    for (int pi = 0; pi < 4; pi++)
        b_off[pi] = (uint32_t)(B_BASE +
            (wn + pi * 16 + (lane & 7) + ((lane >> 4) << 3)) * 80 +
            (((lane >> 3) & 1) << 4));

    float acc[2][8][4];
#pragma unroll
    for (int mi = 0; mi < 2; mi++)
#pragma unroll
        for (int ni = 0; ni < 8; ni++)
#pragma unroll
            for (int r = 0; r < 4; r++) acc[mi][ni][r] = 0.0f;

    issue(0, 0);

    for (int kt = 0; kt < NT; kt++) {
        const int buf = kt & 1;
        if (kt + 1 < NT) { issue(kt + 1, buf ^ 1); cp_wait<1>(); }
        else             { cp_wait<0>(); }
        __syncthreads();

        const uint32_t bo = sbase + buf * BUF_BYTES;
#pragma unroll
        for (int kk = 0; kk < BK; kk += 16) {
            uint32_t afr[2][4], bfr[8][2];
#pragma unroll
            for (int mi = 0; mi < 2; mi++)
                LDSM_X4(afr[mi][0], afr[mi][1], afr[mi][2], afr[mi][3],
                        bo + a_off[mi] + kk * 2);
#pragma unroll
            for (int pi = 0; pi < 4; pi++)
                LDSM_X4(bfr[2 * pi][0], bfr[2 * pi][1], bfr[2 * pi + 1][0], bfr[2 * pi + 1][1],
                        bo + b_off[pi] + kk * 2);
#pragma unroll
            for (int mi = 0; mi < 2; mi++)
#pragma unroll
                for (int ni = 0; ni < 8; ni++) {
                    asm volatile(
                        "mma.sync.aligned.m16n8k16.row.col.f32.f16.f16.f32 "
                        "{%0,%1,%2,%3},{%4,%5,%6,%7},{%8,%9},{%0,%1,%2,%3};"
                        : "+f"(acc[mi][ni][0]), "+f"(acc[mi][ni][1]),
                          "+f"(acc[mi][ni][2]), "+f"(acc[mi][ni][3])
                        : "r"(afr[mi][0]), "r"(afr[mi][1]), "r"(afr[mi][2]), "r"(afr[mi][3]),
                          "r"(bfr[ni][0]), "r"(bfr[ni][1]));
                }
        }
        __syncthreads();
    }

    // Epilogue: c0,c1 -> (row, col..col+1); c2,c3 -> (row+8, ...)
#pragma unroll
    for (int mi = 0; mi < 2; mi++) {
#pragma unroll
        for (int ni = 0; ni < 8; ni++) {
            int row = bm + wm + mi * 16 + (lane >> 2);
            int col = bn + wn + ni * 8 + ((lane & 3) << 1);
            float2 lo = make_float2(acc[mi][ni][0], acc[mi][ni][1]);
            float2 hi = make_float2(acc[mi][ni][2], acc[mi][ni][3]);
            *reinterpret_cast<float2*>(&g_S[(size_t)row * H_DIM + col])       = lo;
            *reinterpret_cast<float2*>(&g_S[(size_t)(row + 8) * H_DIM + col]) = hi;
        }
    }
}

// ---------------- chunked scan: h_t = tanh(a*h + s_t) ----------------
// |a| <= sqrt(2/2048) = 0.03125 -> chunk truncation error <= 0.03125^8 ~ 1e-12.
constexpr int CHUNK  = 32;
constexpr int WARMUP = 8;

__global__ __launch_bounds__(256) void scan_kernel(
    const float* __restrict__ a_mat, float* __restrict__ out)
{
    const int c  = blockIdx.x * blockDim.x + threadIdx.x;
    const int t0 = blockIdx.y * CHUNK;
    const float av = a_mat[c];

    float h = 0.0f;
    int tw = t0 - WARMUP;
    if (tw < 0) tw = 0;
#pragma unroll 4
    for (int t = tw; t < t0; ++t)
        h = tanh_fast(fmaf(av, h, g_S[(size_t)t * H_DIM + c]));
#pragma unroll 8
    for (int t = t0; t < t0 + CHUNK; ++t) {
        h = tanh_fast(fmaf(av, h, g_S[(size_t)t * H_DIM + c]));
        out[(size_t)t * H_DIM + c] = h;
    }
}

// ---------------- launch ----------------
extern "C" void kernel_launch(void* const* d_in, const int* in_sizes, int n_in,
                              void* d_out, int out_size)
{
    const float* x     = (const float*)d_in[0];  // (4096, 2048)
    const float* a_mat = (const float*)d_in[1];  // (2048,)
    const float* b_mat = (const float*)d_in[2];  // (2048, 2048)
    float* out = (float*)d_out;                  // (4096, 2048)

    cudaFuncSetAttribute(gemm_f16_kernel,
                         cudaFuncAttributeMaxDynamicSharedMemorySize, SMEM_BYTES);

    cvt_x_kernel<<<(T_DIM * H_DIM) / (256 * 4), 256>>>(x);
    cvt_bt_kernel<<<dim3(H_DIM / 32, H_DIM / 32), 256>>>(b_mat);

    dim3 gemm_grid(H_DIM / BN, T_DIM / BM);      // (16, 32)
    gemm_f16_kernel<<<gemm_grid, 256, SMEM_BYTES>>>();

    dim3 scan_grid(H_DIM / 256, T_DIM / CHUNK);  // (8, 128)
    scan_kernel<<<scan_grid, 256>>>(a_mat, out);
}

// round 14
// speedup vs baseline: 1.0862x; 1.0468x over previous
#include <cuda_runtime.h>
#include <cuda_fp16.h>
#include <cstdint>

#define T_DIM 4096
#define H_DIM 2048

// __device__ scratch (no allocation allowed)
__device__ float  g_S [T_DIM * H_DIM];   // 32 MB: S = X @ B
__device__ __half g_Bt[H_DIM * H_DIM];   //  8 MB: B^T in fp16 ([n][k])

__device__ __forceinline__ float tanh_fast(float x) {
    float y;
    asm("tanh.approx.f32 %0, %1;" : "=f"(y) : "f"(x));
    return y;
}
__device__ __forceinline__ uint32_t smem_u32(const void* p) {
    return (uint32_t)__cvta_generic_to_shared(p);
}
__device__ __forceinline__ void cp16(uint32_t dst, const void* src) {
    asm volatile("cp.async.cg.shared.global [%0], [%1], 16;" :: "r"(dst), "l"(src));
}
__device__ __forceinline__ void cp_commit() {
    asm volatile("cp.async.commit_group;" ::: "memory");
}
template <int N> __device__ __forceinline__ void cp_wait() {
    asm volatile("cp.async.wait_group %0;" :: "n"(N) : "memory");
}
#define LDSM_X4(r0, r1, r2, r3, addr)                                          \
    asm volatile("ldmatrix.sync.aligned.m8n8.x4.shared.b16 {%0,%1,%2,%3}, [%4];" \
                 : "=r"(r0), "=r"(r1), "=r"(r2), "=r"(r3) : "r"(addr))

// ---------------- pre-pass: B fp32 [k][n] -> fp16 [n][k] ----------------
__global__ __launch_bounds__(256) void cvt_bt_kernel(const float* __restrict__ Bm) {
    __shared__ float tile[32][33];
    const int k0 = blockIdx.y * 32, n0 = blockIdx.x * 32;
    const int x = threadIdx.x & 31, y4 = (threadIdx.x >> 5) << 2;
#pragma unroll
    for (int j = 0; j < 4; j++)
        tile[y4 + j][x] = Bm[(size_t)(k0 + y4 + j) * H_DIM + n0 + x];
    __syncthreads();
#pragma unroll
    for (int j = 0; j < 4; j++)
        g_Bt[(size_t)(n0 + y4 + j) * H_DIM + k0 + x] = __float2half_rn(tile[x][y4 + j]);
}

// ---------------- GEMM: S = X @ B, fp16 m16n8k16 ----------
// Block tile 128(M) x 128(N) x 32(K); 8 warps = 4(M) x 2(N); warp tile 32x64.
// 2 CTAs/SM (__launch_bounds__(256,2)). Mainloop is HMMA-rate bound (~16
// cyc/mma/SMSP on sm_103a legacy path), so A's fp32->fp16 conversion is done
// IN-KERNEL (register-staged LDG one tile ahead, CVT at STS time) at zero
// mainloop cost -- removes the 48 MB cvt_x pre-pass. B arrives pre-transposed
// fp16 via cp.async double-buffering. LDSM-only fragment loads, LDH=40.
constexpr int BM = 128, BN = 128, BK = 32;
constexpr int LDH = 40;
constexpr int A_HALFS = BM * LDH;                   // 5120
constexpr int B_HALFS = BN * LDH;                   // 5120
constexpr int ABUF_B = A_HALFS * 2;                 // 10240 B per A buffer
constexpr int BBUF_B = B_HALFS * 2;                 // 10240 B per B buffer
constexpr int B_BASE = 2 * ABUF_B;                  // B region after 2 A buffers
constexpr int SMEM_BYTES = 2 * (ABUF_B + BBUF_B);   // 40960
constexpr int NT = H_DIM / BK;                      // 64

__global__ __launch_bounds__(256, 2) void gemm_f16_kernel(const float* __restrict__ X)
{
    extern __shared__ __half sh[];
    const uint32_t sbase = smem_u32(sh);

    const int tid  = threadIdx.x;
    const int warp = tid >> 5;
    const int lane = tid & 31;
    const int bm   = blockIdx.y * BM;
    const int bn   = blockIdx.x * BN;
    const int wm   = (warp & 3) * 32;    // 4 M-warps
    const int wn   = (warp >> 2) * 64;   // 2 N-warps

    // A fp32 LDG mapping: 128x32 floats = 1024 float4; 4/thread:
    //   chunk = tid + j*256, row = chunk>>3, c4 = (chunk&7)*4 (float index)
    int a_r[4], a_c4[4];
#pragma unroll
    for (int j = 0; j < 4; j++) { int q = tid + j * 256; a_r[j] = q >> 3; a_c4[j] = (q & 7) << 2; }

    // B cp.async mapping: 128 rows x 32 halves = 512 x 16B chunks, 2/thread.
    const int br0 = tid >> 2, bc8 = (tid & 3) << 3;
    const int br1 = (tid + 256) >> 2;

    float4 a_st[4];
    auto ldgA = [&](int c) {
        const int k0 = c * BK;
#pragma unroll
        for (int j = 0; j < 4; j++)
            a_st[j] = *reinterpret_cast<const float4*>(
                &X[(size_t)(bm + a_r[j]) * H_DIM + k0 + a_c4[j]]);
    };
    auto stsA = [&](int buf) {
        const uint32_t ab = sbase + buf * ABUF_B;
#pragma unroll
        for (int j = 0; j < 4; j++) {
            __half2 lo = __floats2half2_rn(a_st[j].x, a_st[j].y);
            __half2 hi = __floats2half2_rn(a_st[j].z, a_st[j].w);
            uint2 u = make_uint2(*reinterpret_cast<uint32_t*>(&lo),
                                 *reinterpret_cast<uint32_t*>(&hi));
            asm volatile("st.shared.v2.b32 [%0], {%1, %2};"
                         :: "r"(ab + a_r[j] * 80 + a_c4[j] * 2), "r"(u.x), "r"(u.y));
        }
    };
    auto issueB = [&](int c, int buf) {
        const int k0 = c * BK;
        const uint32_t bb = sbase + B_BASE + buf * BBUF_B;
        cp16(bb + br0 * 80 + bc8 * 2, &g_Bt[(size_t)(bn + br0) * H_DIM + k0 + bc8]);
        cp16(bb + br1 * 80 + bc8 * 2, &g_Bt[(size_t)(bn + br1) * H_DIM + k0 + bc8]);
        cp_commit();
    };

    // ldmatrix lane-address byte offsets (within a buffer)
    uint32_t a_off[2], b_off[4];
#pragma unroll
    for (int mi = 0; mi < 2; mi++)
        a_off[mi] = (uint32_t)((wm + mi * 16 + (lane & 15)) * 80 + ((lane >> 4) << 4));
#pragma unroll
    for (int pi = 0; pi < 4; pi++)
        b_off[pi] = (uint32_t)(B_BASE +
            (wn + pi * 16 + (lane & 7) + ((lane >> 4) << 3)) * 80 +
            (((lane >> 3) & 1) << 4));

    float acc[2][8][4];
#pragma unroll
    for (int mi = 0; mi < 2; mi++)
#pragma unroll
        for (int ni = 0; ni < 8; ni++)
#pragma unroll
            for (int r = 0; r < 4; r++) acc[mi][ni][r] = 0.0f;

    // Prologue: stage tile 0 (A via regs+STS, B via cp.async)
    issueB(0, 0);
    ldgA(0);
    stsA(0);

    for (int kt = 0; kt < NT; kt++) {
        const int buf = kt & 1;
        cp_wait<0>();
        __syncthreads();               // A(kt) & B(kt) visible to all warps

        if (kt + 1 < NT) { ldgA(kt + 1); issueB(kt + 1, buf ^ 1); }

        const uint32_t ab = sbase + buf * ABUF_B;
        const uint32_t bb = sbase + buf * BBUF_B;   // b_off includes B_BASE
#pragma unroll
        for (int kk = 0; kk < BK; kk += 16) {
            uint32_t afr[2][4], bfr[8][2];
#pragma unroll
            for (int mi = 0; mi < 2; mi++)
                LDSM_X4(afr[mi][0], afr[mi][1], afr[mi][2], afr[mi][3],
                        ab + a_off[mi] + kk * 2);
#pragma unroll
            for (int pi = 0; pi < 4; pi++)
                LDSM_X4(bfr[2 * pi][0], bfr[2 * pi][1], bfr[2 * pi + 1][0], bfr[2 * pi + 1][1],
                        bb + b_off[pi] + kk * 2);
#pragma unroll
            for (int mi = 0; mi < 2; mi++)
#pragma unroll
                for (int ni = 0; ni < 8; ni++) {
                    asm volatile(
                        "mma.sync.aligned.m16n8k16.row.col.f32.f16.f16.f32 "
                        "{%0,%1,%2,%3},{%4,%5,%6,%7},{%8,%9},{%0,%1,%2,%3};"
                        : "+f"(acc[mi][ni][0]), "+f"(acc[mi][ni][1]),
                          "+f"(acc[mi][ni][2]), "+f"(acc[mi][ni][3])
                        : "r"(afr[mi][0]), "r"(afr[mi][1]), "r"(afr[mi][2]), "r"(afr[mi][3]),
                          "r"(bfr[ni][0]), "r"(bfr[ni][1]));
                }
        }

        if (kt + 1 < NT) stsA(buf ^ 1);  // write other A buffer (drained: its
                                         // readers passed the sync this iter)
    }

    // Epilogue: c0,c1 -> (row, col..col+1); c2,c3 -> (row+8, ...)
#pragma unroll
    for (int mi = 0; mi < 2; mi++) {
#pragma unroll
        for (int ni = 0; ni < 8; ni++) {
            int row = bm + wm + mi * 16 + (lane >> 2);
            int col = bn + wn + ni * 8 + ((lane & 3) << 1);
            float2 lo = make_float2(acc[mi][ni][0], acc[mi][ni][1]);
            float2 hi = make_float2(acc[mi][ni][2], acc[mi][ni][3]);
            *reinterpret_cast<float2*>(&g_S[(size_t)row * H_DIM + col])       = lo;
            *reinterpret_cast<float2*>(&g_S[(size_t)(row + 8) * H_DIM + col]) = hi;
        }
    }
}

// ---------------- chunked scan: h_t = tanh(a*h + s_t) ----------------
// |a| <= sqrt(2/2048) = 0.03125 -> chunk truncation error <= 0.03125^8 ~ 1e-12.
constexpr int CHUNK  = 32;
constexpr int WARMUP = 8;

__global__ __launch_bounds__(256) void scan_kernel(
    const float* __restrict__ a_mat, float* __restrict__ out)
{
    const int c  = blockIdx.x * blockDim.x + threadIdx.x;
    const int t0 = blockIdx.y * CHUNK;
    const float av = a_mat[c];

    float h = 0.0f;
    int tw = t0 - WARMUP;
    if (tw < 0) tw = 0;
#pragma unroll 4
    for (int t = tw; t < t0; ++t)
        h = tanh_fast(fmaf(av, h, g_S[(size_t)t * H_DIM + c]));
#pragma unroll 8
    for (int t = t0; t < t0 + CHUNK; ++t) {
        h = tanh_fast(fmaf(av, h, g_S[(size_t)t * H_DIM + c]));
        out[(size_t)t * H_DIM + c] = h;
    }
}

// ---------------- launch ----------------
extern "C" void kernel_launch(void* const* d_in, const int* in_sizes, int n_in,
                              void* d_out, int out_size)
{
    const float* x     = (const float*)d_in[0];  // (4096, 2048)
    const float* a_mat = (const float*)d_in[1];  // (2048,)
    const float* b_mat = (const float*)d_in[2];  // (2048, 2048)
    float* out = (float*)d_out;                  // (4096, 2048)

    cudaFuncSetAttribute(gemm_f16_kernel,
                         cudaFuncAttributeMaxDynamicSharedMemorySize, SMEM_BYTES);

    cvt_bt_kernel<<<dim3(H_DIM / 32, H_DIM / 32), 256>>>(b_mat);

    dim3 gemm_grid(H_DIM / BN, T_DIM / BM);      // (16, 32)
    gemm_f16_kernel<<<gemm_grid, 256, SMEM_BYTES>>>(x);

    dim3 scan_grid(H_DIM / 256, T_DIM / CHUNK);  // (8, 128)
    scan_kernel<<<scan_grid, 256>>>(a_mat, out);
}